// round 12
// baseline (speedup 1.0000x reference)
#include <cuda_runtime.h>
#include <math.h>

#define BB 8
#define QQ 2048
#define GG 128
#define CC 512
#define TOPK 128     // exactly sufficient: <=127 cols matched at probe time
#define MCW 136      // Mc row stride (floats): 16B-aligned float4, conflict-free
#define M26 0x3FFFFFFull   // low 26 key bits: col(12)|row(7)|slot(7)
#define EPS_AMB 1e-3f      // fp32-selection safety margin (10x worst-case err)

// Transposed cost scratch: [b][g][q], contiguous in q (feeds the sort).
__device__ float g_costT[BB * GG * QQ];
// Per (b,row) sorted smallest-TOPK entries, packed (ord32(val)<<32)|col(1-based).
__device__ unsigned long long g_top[BB * GG * TOPK];

// ---------------------------------------------------------------------------
__device__ __forceinline__ unsigned int ord32(float f) {
    unsigned int u = __float_as_uint(f);
    return (u & 0x80000000u) ? ~u : (u | 0x80000000u);
}
__device__ __forceinline__ float unord32(unsigned int o) {
    unsigned int u = (o & 0x80000000u) ? (o ^ 0x80000000u) : ~o;
    return __uint_as_float(u);
}
__device__ __forceinline__ unsigned long long ord64(double d) {
    unsigned long long u = (unsigned long long)__double_as_longlong(d);
    return (u >> 63) ? ~u : (u | 0x8000000000000000ull);
}

// ---------------------------------------------------------------------------
// Kernel 1: fused focal-class cost + regression costs, tiled transpose.
// ---------------------------------------------------------------------------
__global__ void __launch_bounds__(256)
cost_kernel(const float* __restrict__ sem,
            const float* __restrict__ cen,
            const float* __restrict__ siz,
            const float* __restrict__ gio,
            const int* __restrict__ lab,
            float* __restrict__ out_cost) {
    __shared__ float tile[32][33];
    __shared__ int   lab_s[32];

    int blk = blockIdx.x;                 // (b * 4 + gt) * 64 + qt
    int qt  = blk & 63;
    int gt  = (blk >> 6) & 3;
    int b   = blk >> 8;

    int tx = threadIdx.x & 31;            // g within tile
    int ty = threadIdx.x >> 5;            // q sub-row (0..7)
    int g0 = gt * 32;
    int q0 = qt * 32;

    if (threadIdx.x < 32) lab_s[tx] = lab[b * GG + g0 + tx];
    __syncthreads();

    int l = lab_s[tx];
    #pragma unroll
    for (int s = 0; s < 4; ++s) {
        int ql = ty + 8 * s;
        int q  = q0 + ql;
        long long idx = ((long long)(b * QQ + q)) * GG + g0 + tx;

        float x = sem[((long long)(b * QQ + q)) * CC + l];
        float p   = 1.0f / (1.0f + expf(-x));
        float neg = 0.75f * p * p * (-log1pf(-(p - 1e-8f)));
        float pos = 0.25f * (1.0f - p) * (1.0f - p) * (-logf(p + 1e-8f));
        float cost = 2.0f * (pos - neg) + 5.0f * cen[idx] + siz[idx]
                     - 2.0f * gio[idx];

        out_cost[idx] = cost;
        tile[ql][tx]  = cost;
    }
    __syncthreads();

    #pragma unroll
    for (int s = 0; s < 4; ++s) {
        int gl = ty + 8 * s;
        g_costT[((long long)(b * GG + g0 + gl)) * QQ + q0 + tx] = tile[tx][gl];
    }
}

// ---------------------------------------------------------------------------
// Kernel 2: per (b,row) bitonic sort of 2048 packed keys. Phases jj>=32 in
// shared; phases jj<=16 in registers via shfl (no barriers). Keep TOPK.
// ---------------------------------------------------------------------------
__global__ void __launch_bounds__(1024)
sort_kernel() {
    __shared__ unsigned long long s[QQ];
    const unsigned FULL = 0xffffffffu;
    int tid = threadIdx.x;
    const float* rowp = g_costT + (size_t)blockIdx.x * QQ;

    s[tid] = ((unsigned long long)ord32(rowp[tid]) << 32) |
             (unsigned int)(tid + 1);
    s[tid + 1024] = ((unsigned long long)ord32(rowp[tid + 1024]) << 32) |
                    (unsigned int)(tid + 1024 + 1);
    __syncthreads();

    for (int k = 2; k <= QQ; k <<= 1) {
        for (int jj = k >> 1; jj >= 32; jj >>= 1) {
            int low = tid & (jj - 1);
            int i   = ((tid & ~(jj - 1)) << 1) | low;
            int l   = i | jj;
            unsigned long long a = s[i], c = s[l];
            bool asc = ((i & k) == 0);
            if (asc ? (a > c) : (a < c)) { s[i] = c; s[l] = a; }
            __syncthreads();
        }
        int idx0 = tid, idx1 = tid + 1024;
        unsigned long long e0 = s[idx0], e1 = s[idx1];
        bool asc0 = ((idx0 & k) == 0);
        bool asc1 = ((idx1 & k) == 0);
        int jj0 = (k >> 1 < 32) ? (k >> 1) : 16;
        for (int jj = jj0; jj > 0; jj >>= 1) {
            unsigned long long p0 = __shfl_xor_sync(FULL, e0, jj);
            unsigned long long p1 = __shfl_xor_sync(FULL, e1, jj);
            bool keepmin0 = (((idx0 & jj) == 0) == asc0);
            bool keepmin1 = (((idx1 & jj) == 0) == asc1);
            if (keepmin0 ? (p0 < e0) : (p0 > e0)) e0 = p0;
            if (keepmin1 ? (p1 < e1) : (p1 > e1)) e1 = p1;
        }
        s[idx0] = e0; s[idx1] = e1;
        __syncthreads();
    }
    if (tid < TOPK)
        g_top[(size_t)blockIdx.x * TOPK + tid] = s[tid];
}

// ---------------------------------------------------------------------------
// Kernel 3: one warp per batch; reference's degenerate e-maxx loop.
// Probe caches are repaired EAGERLY at augmentation (lane-parallel, off the
// critical path) so the selection loop never refreshes. fp32 fast selection
// with exact-fp64 ambiguity fallback; exact fp64 accounting.
// ---------------------------------------------------------------------------
struct SmemLSA {
    unsigned long long top_s[GG * TOPK];   // 131072 B (16B-aligned first)
    unsigned long long pc[GG + 2];         // raw sorted entry (ord32<<32|col)
    float  Mc[GG * MCW];                   // row-major [row-1][slot]
    double u_s[GG + 2];
    double Dj[GG + 4];
    int    chain_slot[GG + 4];
    int    chain_row[GG + 4];
    int    cursor[GG + 2];
    unsigned int colinfo[QQ + 4]; // 0 = unmatched; else row (for repair/emit)
};

__global__ void __launch_bounds__(32, 1)
lsa_kernel(const int* __restrict__ nactual,
           const float* __restrict__ cost_bqg,
           float* __restrict__ out_inds,
           float* __restrict__ out_mask) {
    extern __shared__ unsigned char smraw[];
    SmemLSA& S = *reinterpret_cast<SmemLSA*>(smraw);

    const unsigned FULL = 0xffffffffu;
    int b    = blockIdx.x;
    int lane = threadIdx.x;
    int n = nactual[b];
    if (n > GG) n = GG;
    if (n < 0) n = 0;

    // preload the full sorted top-list into shared (16B vectorized, coalesced)
    {
        const ulonglong2* src =
            (const ulonglong2*)(g_top + (size_t)b * GG * TOPK);
        ulonglong2* dst = (ulonglong2*)S.top_s;
        #pragma unroll 8
        for (int t = lane; t < GG * TOPK / 2; t += 32)
            dst[t] = __ldg(&src[t]);
    }
    for (int t = lane; t < GG + 2; t += 32) { S.u_s[t] = 0.0; S.cursor[t] = 0; }
    for (int t = lane; t < QQ + 4; t += 32) S.colinfo[t] = 0u;
    __syncwarp();
    // init probe caches: first sorted entry of each row (nothing matched yet)
    #pragma unroll
    for (int t = 0; t < 4; ++t) {
        int r = 1 + lane + 32 * t;
        S.pc[r] = S.top_s[(r - 1) * TOPK];
    }
    __syncwarp();

    const float* costb = cost_bqg + (size_t)b * QQ * GG;

    // Per-lane slot state: lane owns slots 4*lane .. 4*lane+3.
    double   v_r[4];
    float    vf_r[4];
    unsigned low_r[4];            // col<<14 | (row-1)<<7 | slot
    int mcount = 0;

    for (int i = 1; i <= n; ++i) {
        unsigned um = 0;
        int cl = 1, row = i, j1;
        double D = 0.0;
        if (lane == 0) { S.chain_row[0] = i; S.Dj[0] = 0.0; }
        __syncwarp();

        while (true) {
            // --- probe: always-valid cached entry, one broadcast LDS.64 ---
            unsigned long long pe = S.pc[row];
            unsigned pcc_u = (unsigned)(pe & 0xFFFFFFFFull);
            unsigned phi   = (unsigned)(pe >> 32);          // ord32(val)
            double u_row = S.u_s[row];

            // --- fp32 fast keys: one LDS.128 + FADD, packed (ord32|id26) ---
            const float4 mc = *(const float4*)&S.Mc[(row - 1) * MCW + 4 * lane];
            float mcf[4] = {mc.x, mc.y, mc.z, mc.w};
            bool  act[4];
            float kf[4];
            unsigned long long kk[4];
            int base = 4 * lane;
            #pragma unroll
            for (int t = 0; t < 4; ++t) {
                act[t] = (base + t < mcount) && !((um >> t) & 1u);
                kf[t]  = act[t] ? (mcf[t] - vf_r[t]) : __int_as_float(0x7F800000);
                kk[t]  = ((unsigned long long)ord32(kf[t]) << 32) | low_r[t];
            }
            unsigned long long a0 = (kk[0] < kk[1]) ? kk[0] : kk[1];
            unsigned long long a1 = (kk[2] < kk[3]) ? kk[2] : kk[3];
            unsigned long long bk = (a0 < a1) ? a0 : a1;
            if (lane == 0) {
                unsigned long long kp =
                    ((unsigned long long)phi << 32) | (pcc_u << 14) | 0x7Fu;
                if (kp < bk) bk = kp;
            }

            // --- 2-stage REDUX argmin on fp32 keys ---
            unsigned hi   = (unsigned)(bk >> 32);
            unsigned hmin = __reduce_min_sync(FULL, hi);
            unsigned lo   = (hi == hmin) ? (unsigned)bk : 0xFFFFFFFFu;
            unsigned lmin = __reduce_min_sync(FULL, lo);

            // --- ambiguity check: >=2 candidates within EPS of the min ---
            float thr = unord32(hmin) + EPS_AMB;
            unsigned cnt = 0;
            #pragma unroll
            for (int t = 0; t < 4; ++t)
                if (act[t] && kf[t] <= thr) ++cnt;
            if (lane == 0 && unord32(phi) <= thr) ++cnt;
            unsigned tot = __reduce_add_sync(FULL, cnt);

            if (tot >= 2) {
                // --- exact fp64 fallback (proven path) ---
                float pval = unord32(phi);
                unsigned long long k2[4];
                #pragma unroll
                for (int t = 0; t < 4; ++t)
                    k2[t] = act[t]
                        ? ((ord64((double)mcf[t] - v_r[t]) & ~M26) | low_r[t])
                        : ~0ull;
                unsigned long long c0 = (k2[0] < k2[1]) ? k2[0] : k2[1];
                unsigned long long c1 = (k2[2] < k2[3]) ? k2[2] : k2[3];
                unsigned long long b2 = (c0 < c1) ? c0 : c1;
                if (lane == 0) {
                    unsigned long long kp2 = (ord64((double)pval) & ~M26)
                                             | (pcc_u << 14) | 0x7Fu;
                    if (kp2 < b2) b2 = kp2;
                }
                unsigned h2  = (unsigned)(b2 >> 32);
                unsigned hm2 = __reduce_min_sync(FULL, h2);
                unsigned l2  = (h2 == hm2) ? (unsigned)b2 : 0xFFFFFFFFu;
                lmin = __reduce_min_sync(FULL, l2);
            }

            int slot1 = (int)(lmin & 0x7Fu);
            j1 = (int)((lmin >> 14) & 0xFFFu);

            // --- exact D update via owner-lane recompute (off critical path) ---
            int owner = (slot1 == 0x7F) ? 0 : (slot1 >> 2);
            double ek = 0.0;
            if (lane == owner) {
                if (slot1 == 0x7F) ek = (double)unord32(phi);
                else {
                    int t = slot1 & 3;
                    float mm; double vv;
                    switch (t) {
                        case 0: mm = mcf[0]; vv = v_r[0]; break;
                        case 1: mm = mcf[1]; vv = v_r[1]; break;
                        case 2: mm = mcf[2]; vv = v_r[2]; break;
                        default: mm = mcf[3]; vv = v_r[3]; break;
                    }
                    ek = (double)mm - vv;
                }
            }
            ek = __shfl_sync(FULL, ek, owner);
            D += ek - u_row;

            if (slot1 != 0x7F) {          // chase occupied column
                int nrow = (int)((lmin >> 7) & 0x7Fu) + 1;
                if (owner == lane) um |= 1u << (slot1 & 3);
                if (lane == 0) {
                    S.chain_slot[cl] = slot1;
                    S.chain_row[cl]  = nrow;
                    S.Dj[cl]         = D;
                }
                row = nrow;
                ++cl;
            } else break;                 // free column: augment
        }
        __syncwarp();

        // ---- augmentation (off critical path) ----
        {
            const float* colp = costb + (size_t)(j1 - 1) * GG;
            #pragma unroll
            for (int m = 0; m < 4; ++m) {
                int r = lane + 32 * m;
                S.Mc[r * MCW + mcount] = __ldg(&colp[r]);
            }
        }
        for (int t = lane; t < cl; t += 32) {
            S.u_s[S.chain_row[t]] += D - S.Dj[t];
        }
        for (int t = 1; t < cl; ++t) {
            int s = S.chain_slot[t];
            if ((s >> 2) == lane) {
                double acc = D - S.Dj[t];
                switch (s & 3) {
                    case 0: v_r[0] -= acc; break;
                    case 1: v_r[1] -= acc; break;
                    case 2: v_r[2] -= acc; break;
                    case 3: v_r[3] -= acc; break;
                }
            }
        }
        if ((mcount >> 2) == lane) {
            unsigned lw = ((unsigned)j1 << 14) | ((unsigned)(i - 1) << 7)
                          | (unsigned)mcount;
            switch (mcount & 3) {
                case 0: v_r[0] = 0.0; low_r[0] = lw; break;
                case 1: v_r[1] = 0.0; low_r[1] = lw; break;
                case 2: v_r[2] = 0.0; low_r[2] = lw; break;
                case 3: v_r[3] = 0.0; low_r[3] = lw; break;
            }
        }
        #pragma unroll
        for (int t = 0; t < 4; ++t) vf_r[t] = (float)v_r[t];

        if (lane == 0) S.colinfo[j1] = (unsigned)i;   // row, for repair/emit
        ++mcount;
        __syncwarp();

        // ---- eager probe-cache repair (lane-parallel, off critical path) ----
        // Rows whose cached candidate just got matched rescan from cursor+1.
        #pragma unroll
        for (int t = 0; t < 4; ++t) {
            int r = 1 + lane + 32 * t;
            if ((unsigned)(S.pc[r] & 0xFFFFFFFFull) == (unsigned)j1) {
                const unsigned long long* trow = S.top_s + (r - 1) * TOPK;
                int idx = S.cursor[r] + 1;
                unsigned long long e = ~0ull;
                while (idx < TOPK) {
                    e = trow[idx];
                    if (S.colinfo[(unsigned)(e & 0xFFFFFFFFull)] == 0u) break;
                    ++idx;
                }
                if (idx >= TOPK) e = ~0ull;   // exhausted (only at mcount==128)
                S.pc[r]     = e;
                S.cursor[r] = idx;
            }
        }
        __syncwarp();
    }

    // emit per-proposal matches
    for (int j = lane; j < QQ; j += 32) {
        unsigned info = S.colinfo[j + 1];
        float ind = 0.0f, mskv = 0.0f;
        if (info) { ind = (float)(info - 1); mskv = 1.0f; }
        out_inds[b * QQ + j] = ind;
        out_mask[b * QQ + j] = mskv;
    }
}

// ---------------------------------------------------------------------------
extern "C" void kernel_launch(void* const* d_in, const int* in_sizes, int n_in,
                              void* d_out, int out_size) {
    const float* sem = (const float*)d_in[0];
    const float* cen = (const float*)d_in[1];
    const float* siz = (const float*)d_in[2];
    const float* gio = (const float*)d_in[3];
    const int*   lab = (const int*)d_in[4];
    const int*   na  = (const int*)d_in[5];

    float* out = (float*)d_out;
    const int NI = BB * QQ;
    const int NC = BB * QQ * GG;

    float* out_inds = out;
    float* out_mask = out + NI;
    float* out_cost = out + 2 * NI;
    bool   do_lsa   = true;
    if (out_size == NC) { out_cost = out; do_lsa = false; }

    cost_kernel<<<BB * 4 * 64, 256>>>(sem, cen, siz, gio, lab, out_cost);
    if (do_lsa) {
        sort_kernel<<<BB * GG, 1024>>>();
        static bool attr_set = false;
        if (!attr_set) {
            cudaFuncSetAttribute(lsa_kernel,
                                 cudaFuncAttributeMaxDynamicSharedMemorySize,
                                 (int)sizeof(SmemLSA));
            attr_set = true;
        }
        lsa_kernel<<<BB, 32, sizeof(SmemLSA)>>>(na, out_cost, out_inds, out_mask);
    }
}

// round 13
// speedup vs baseline: 1.1256x; 1.1256x over previous
#include <cuda_runtime.h>
#include <math.h>

#define BB 8
#define QQ 2048
#define GG 128
#define CC 512
#define TOPK 128     // exactly sufficient: <=127 cols matched at probe time
#define MCW 136      // Mc row stride (floats): 16B-aligned float4, conflict-free
#define M26 0x3FFFFFFull   // low 26 key bits: col(12)|row(7)|slot(7)
#define EPS_AMB 1e-3f      // fp32-selection safety margin (10x worst-case err)

// Transposed cost scratch: [b][g][q], contiguous in q (feeds the sort).
__device__ float g_costT[BB * GG * QQ];
// Per (b,row) sorted smallest-TOPK entries, packed (ord32(val)<<32)|col(1-based).
__device__ unsigned long long g_top[BB * GG * TOPK];

// ---------------------------------------------------------------------------
__device__ __forceinline__ unsigned int ord32(float f) {
    unsigned int u = __float_as_uint(f);
    return (u & 0x80000000u) ? ~u : (u | 0x80000000u);
}
__device__ __forceinline__ float unord32(unsigned int o) {
    unsigned int u = (o & 0x80000000u) ? (o ^ 0x80000000u) : ~o;
    return __uint_as_float(u);
}
__device__ __forceinline__ unsigned long long ord64(double d) {
    unsigned long long u = (unsigned long long)__double_as_longlong(d);
    return (u >> 63) ? ~u : (u | 0x8000000000000000ull);
}

// ---------------------------------------------------------------------------
// Kernel 1: fused focal-class cost + regression costs, tiled transpose.
// ---------------------------------------------------------------------------
__global__ void __launch_bounds__(256)
cost_kernel(const float* __restrict__ sem,
            const float* __restrict__ cen,
            const float* __restrict__ siz,
            const float* __restrict__ gio,
            const int* __restrict__ lab,
            float* __restrict__ out_cost) {
    __shared__ float tile[32][33];
    __shared__ int   lab_s[32];

    int blk = blockIdx.x;                 // (b * 4 + gt) * 64 + qt
    int qt  = blk & 63;
    int gt  = (blk >> 6) & 3;
    int b   = blk >> 8;

    int tx = threadIdx.x & 31;            // g within tile
    int ty = threadIdx.x >> 5;            // q sub-row (0..7)
    int g0 = gt * 32;
    int q0 = qt * 32;

    if (threadIdx.x < 32) lab_s[tx] = lab[b * GG + g0 + tx];
    __syncthreads();

    int l = lab_s[tx];
    #pragma unroll
    for (int s = 0; s < 4; ++s) {
        int ql = ty + 8 * s;
        int q  = q0 + ql;
        long long idx = ((long long)(b * QQ + q)) * GG + g0 + tx;

        float x = sem[((long long)(b * QQ + q)) * CC + l];
        float p   = 1.0f / (1.0f + expf(-x));
        float neg = 0.75f * p * p * (-log1pf(-(p - 1e-8f)));
        float pos = 0.25f * (1.0f - p) * (1.0f - p) * (-logf(p + 1e-8f));
        float cost = 2.0f * (pos - neg) + 5.0f * cen[idx] + siz[idx]
                     - 2.0f * gio[idx];

        out_cost[idx] = cost;
        tile[ql][tx]  = cost;
    }
    __syncthreads();

    #pragma unroll
    for (int s = 0; s < 4; ++s) {
        int gl = ty + 8 * s;
        g_costT[((long long)(b * GG + g0 + gl)) * QQ + q0 + tx] = tile[tx][gl];
    }
}

// ---------------------------------------------------------------------------
// Kernel 2: per (b,row) bitonic sort of 2048 packed keys. Phases jj>=32 in
// shared; phases jj<=16 in registers via shfl (no barriers). Keep TOPK.
// ---------------------------------------------------------------------------
__global__ void __launch_bounds__(1024)
sort_kernel() {
    __shared__ unsigned long long s[QQ];
    const unsigned FULL = 0xffffffffu;
    int tid = threadIdx.x;
    const float* rowp = g_costT + (size_t)blockIdx.x * QQ;

    s[tid] = ((unsigned long long)ord32(rowp[tid]) << 32) |
             (unsigned int)(tid + 1);
    s[tid + 1024] = ((unsigned long long)ord32(rowp[tid + 1024]) << 32) |
                    (unsigned int)(tid + 1024 + 1);
    __syncthreads();

    for (int k = 2; k <= QQ; k <<= 1) {
        for (int jj = k >> 1; jj >= 32; jj >>= 1) {
            int low = tid & (jj - 1);
            int i   = ((tid & ~(jj - 1)) << 1) | low;
            int l   = i | jj;
            unsigned long long a = s[i], c = s[l];
            bool asc = ((i & k) == 0);
            if (asc ? (a > c) : (a < c)) { s[i] = c; s[l] = a; }
            __syncthreads();
        }
        int idx0 = tid, idx1 = tid + 1024;
        unsigned long long e0 = s[idx0], e1 = s[idx1];
        bool asc0 = ((idx0 & k) == 0);
        bool asc1 = ((idx1 & k) == 0);
        int jj0 = (k >> 1 < 32) ? (k >> 1) : 16;
        for (int jj = jj0; jj > 0; jj >>= 1) {
            unsigned long long p0 = __shfl_xor_sync(FULL, e0, jj);
            unsigned long long p1 = __shfl_xor_sync(FULL, e1, jj);
            bool keepmin0 = (((idx0 & jj) == 0) == asc0);
            bool keepmin1 = (((idx1 & jj) == 0) == asc1);
            if (keepmin0 ? (p0 < e0) : (p0 > e0)) e0 = p0;
            if (keepmin1 ? (p1 < e1) : (p1 > e1)) e1 = p1;
        }
        s[idx0] = e0; s[idx1] = e1;
        __syncthreads();
    }
    if (tid < TOPK)
        g_top[(size_t)blockIdx.x * TOPK + tid] = s[tid];
}

// ---------------------------------------------------------------------------
// Kernel 3: one warp per batch; reference's degenerate e-maxx loop.
// fp32 fast selection + exact-fp64 ambiguity fallback (ballot-based check);
// exact fp64 accounting; lazy probe refresh; augmentation LDG latency hidden
// by issuing column loads before all other bookkeeping.
// ---------------------------------------------------------------------------
struct SmemLSA {
    unsigned long long top_s[GG * TOPK];   // 131072 B (16B-aligned first)
    float  Mc[GG * MCW];                   // row-major [row-1][slot]
    double u_s[GG + 2];
    double Dj[GG + 4];
    int    chain_slot[GG + 4];
    int    chain_row[GG + 4];
    int    pc_col[GG + 2];        // cached first-unmatched col per row (0=none)
    float  pc_val[GG + 2];
    int    cursor[GG + 2];
    unsigned int colinfo[QQ + 4]; // 0 = unmatched; else row (for ballot/emit)
};

__global__ void __launch_bounds__(32, 1)
lsa_kernel(const int* __restrict__ nactual,
           const float* __restrict__ cost_bqg,
           float* __restrict__ out_inds,
           float* __restrict__ out_mask) {
    extern __shared__ unsigned char smraw[];
    SmemLSA& S = *reinterpret_cast<SmemLSA*>(smraw);

    const unsigned FULL = 0xffffffffu;
    int b    = blockIdx.x;
    int lane = threadIdx.x;
    int n = nactual[b];
    if (n > GG) n = GG;
    if (n < 0) n = 0;

    // preload the full sorted top-list into shared (16B vectorized, coalesced)
    {
        const ulonglong2* src =
            (const ulonglong2*)(g_top + (size_t)b * GG * TOPK);
        ulonglong2* dst = (ulonglong2*)S.top_s;
        #pragma unroll 8
        for (int t = lane; t < GG * TOPK / 2; t += 32)
            dst[t] = __ldg(&src[t]);
    }
    for (int t = lane; t < GG + 2; t += 32) {
        S.u_s[t] = 0.0; S.pc_col[t] = 0; S.cursor[t] = 0;
    }
    for (int t = lane; t < QQ + 4; t += 32) S.colinfo[t] = 0u;
    __syncwarp();

    const float* costb = cost_bqg + (size_t)b * QQ * GG;

    // Per-lane slot state: lane owns slots 4*lane .. 4*lane+3.
    double   v_r[4];
    float    vf_r[4];
    unsigned low_r[4];            // col<<14 | (row-1)<<7 | slot
    int mcount = 0;

    for (int i = 1; i <= n; ++i) {
        unsigned um = 0;
        int cl = 1, row = i, j1;
        double D = 0.0;
        if (lane == 0) { S.chain_row[0] = i; S.Dj[0] = 0.0; }
        __syncwarp();

        while (true) {
            // --- probe: cached first-unmatched entry; lazy refresh from SMEM ---
            int   pcc;
            float pval;
            {
                int c0 = S.pc_col[row];
                if (c0 != 0) {
                    pcc = c0; pval = S.pc_val[row];
                } else {
                    const unsigned long long* trow = S.top_s + (row - 1) * TOPK;
                    int cur = S.cursor[row];
                    unsigned long long ew = 0;
                    for (int r = cur >> 5; r < TOPK / 32; ++r) {
                        unsigned long long e = trow[r * 32 + lane];
                        int c = (int)(unsigned int)(e & 0xFFFFFFFFu);
                        unsigned m = __ballot_sync(FULL, S.colinfo[c] == 0u);
                        if (m) {
                            int f = __ffs(m) - 1;
                            ew = __shfl_sync(FULL, e, f);
                            if (lane == 0) S.cursor[row] = r * 32 + f;
                            break;
                        }
                    }
                    pcc  = (int)(unsigned int)(ew & 0xFFFFFFFFu);
                    pval = unord32((unsigned int)(ew >> 32));
                    if (lane == 0) {
                        S.pc_col[row] = pcc;
                        S.pc_val[row] = pval;
                    }
                    __syncwarp();
                }
            }
            double u_row = S.u_s[row];

            // --- fp32 fast keys: one LDS.128 + FADD, packed (ord32|id26) ---
            const float4 mc = *(const float4*)&S.Mc[(row - 1) * MCW + 4 * lane];
            float mcf[4] = {mc.x, mc.y, mc.z, mc.w};
            bool  act[4];
            float kf[4];
            unsigned long long kk[4];
            int base = 4 * lane;
            #pragma unroll
            for (int t = 0; t < 4; ++t) {
                act[t] = (base + t < mcount) && !((um >> t) & 1u);
                kf[t]  = act[t] ? (mcf[t] - vf_r[t]) : __int_as_float(0x7F800000);
                kk[t]  = ((unsigned long long)ord32(kf[t]) << 32) | low_r[t];
            }
            unsigned long long a0 = (kk[0] < kk[1]) ? kk[0] : kk[1];
            unsigned long long a1 = (kk[2] < kk[3]) ? kk[2] : kk[3];
            unsigned long long bk = (a0 < a1) ? a0 : a1;
            if (lane == 0) {
                unsigned long long kp =
                    ((unsigned long long)ord32(pval) << 32)
                    | ((unsigned)pcc << 14) | 0x7Fu;
                if (kp < bk) bk = kp;
            }

            // --- 2-stage REDUX argmin on fp32 keys ---
            unsigned hi   = (unsigned)(bk >> 32);
            unsigned hmin = __reduce_min_sync(FULL, hi);
            unsigned lo   = (hi == hmin) ? (unsigned)bk : 0xFFFFFFFFu;
            unsigned lmin = __reduce_min_sync(FULL, lo);

            // --- ambiguity check via ballots: >=2 candidates within EPS ---
            float thr = unord32(hmin) + EPS_AMB;
            unsigned cnt = 0;
            #pragma unroll
            for (int t = 0; t < 4; ++t)
                if (act[t] && kf[t] <= thr) ++cnt;
            if (lane == 0 && pval <= thr) ++cnt;
            unsigned m1 = __ballot_sync(FULL, cnt >= 1u);
            unsigned m2 = __ballot_sync(FULL, cnt >= 2u);
            bool ambig = (m2 != 0u) | (__popc(m1) >= 2);

            if (ambig) {
                // --- exact fp64 fallback (proven path) ---
                unsigned long long k2[4];
                #pragma unroll
                for (int t = 0; t < 4; ++t)
                    k2[t] = act[t]
                        ? ((ord64((double)mcf[t] - v_r[t]) & ~M26) | low_r[t])
                        : ~0ull;
                unsigned long long c0 = (k2[0] < k2[1]) ? k2[0] : k2[1];
                unsigned long long c1 = (k2[2] < k2[3]) ? k2[2] : k2[3];
                unsigned long long b2 = (c0 < c1) ? c0 : c1;
                if (lane == 0) {
                    unsigned long long kp2 = (ord64((double)pval) & ~M26)
                                             | ((unsigned)pcc << 14) | 0x7Fu;
                    if (kp2 < b2) b2 = kp2;
                }
                unsigned h2  = (unsigned)(b2 >> 32);
                unsigned hm2 = __reduce_min_sync(FULL, h2);
                unsigned l2  = (h2 == hm2) ? (unsigned)b2 : 0xFFFFFFFFu;
                lmin = __reduce_min_sync(FULL, l2);
            }

            int slot1 = (int)(lmin & 0x7Fu);
            j1 = (int)((lmin >> 14) & 0xFFFu);

            // --- exact D update via owner-lane recompute (off critical path) ---
            int owner = (slot1 == 0x7F) ? 0 : (slot1 >> 2);
            double ek = 0.0;
            if (lane == owner) {
                if (slot1 == 0x7F) ek = (double)pval;
                else {
                    int t = slot1 & 3;
                    float mm; double vv;
                    switch (t) {
                        case 0: mm = mcf[0]; vv = v_r[0]; break;
                        case 1: mm = mcf[1]; vv = v_r[1]; break;
                        case 2: mm = mcf[2]; vv = v_r[2]; break;
                        default: mm = mcf[3]; vv = v_r[3]; break;
                    }
                    ek = (double)mm - vv;
                }
            }
            ek = __shfl_sync(FULL, ek, owner);
            D += ek - u_row;

            if (slot1 != 0x7F) {          // chase occupied column
                int nrow = (int)((lmin >> 7) & 0x7Fu) + 1;
                if (owner == lane) um |= 1u << (slot1 & 3);
                if (lane == 0) {
                    S.chain_slot[cl] = slot1;
                    S.chain_row[cl]  = nrow;
                    S.Dj[cl]         = D;
                }
                row = nrow;
                ++cl;
            } else break;                 // free column: augment
        }
        __syncwarp();

        // ---- augmentation: issue column LDGs FIRST, bookkeeping in their
        //      shadow, STS last — hides the ~250cyc L2 round-trip ----
        float mcol[4];
        {
            const float* colp = costb + (size_t)(j1 - 1) * GG;
            #pragma unroll
            for (int m = 0; m < 4; ++m)
                mcol[m] = __ldg(&colp[lane + 32 * m]);
        }
        // deferred u updates (chain rows distinct)
        for (int t = lane; t < cl; t += 32) {
            S.u_s[S.chain_row[t]] += D - S.Dj[t];
        }
        // deferred v updates: each lane applies chain entries owning its slots
        for (int t = 1; t < cl; ++t) {
            int s = S.chain_slot[t];
            if ((s >> 2) == lane) {
                double acc = D - S.Dj[t];
                switch (s & 3) {
                    case 0: v_r[0] -= acc; break;
                    case 1: v_r[1] -= acc; break;
                    case 2: v_r[2] -= acc; break;
                    case 3: v_r[3] -= acc; break;
                }
            }
        }
        // invalidate probe caches pointing at the newly matched column
        #pragma unroll
        for (int t = 0; t < 4; ++t) {
            int r = 1 + lane + 32 * t;
            if (S.pc_col[r] == j1) S.pc_col[r] = 0;
        }
        // register the new slot (low bits precomputed for key packing)
        if ((mcount >> 2) == lane) {
            unsigned lw = ((unsigned)j1 << 14) | ((unsigned)(i - 1) << 7)
                          | (unsigned)mcount;
            switch (mcount & 3) {
                case 0: v_r[0] = 0.0; low_r[0] = lw; break;
                case 1: v_r[1] = 0.0; low_r[1] = lw; break;
                case 2: v_r[2] = 0.0; low_r[2] = lw; break;
                case 3: v_r[3] = 0.0; low_r[3] = lw; break;
            }
        }
        // refresh float copies of v (cheap, off path)
        #pragma unroll
        for (int t = 0; t < 4; ++t) vf_r[t] = (float)v_r[t];

        if (lane == 0) S.colinfo[j1] = (unsigned)i;   // row, for ballot/emit

        // Mc fill last: LDG results have had ~100+ cycles to land
        #pragma unroll
        for (int m = 0; m < 4; ++m)
            S.Mc[(lane + 32 * m) * MCW + mcount] = mcol[m];

        ++mcount;
        __syncwarp();
    }

    // emit per-proposal matches
    for (int j = lane; j < QQ; j += 32) {
        unsigned info = S.colinfo[j + 1];
        float ind = 0.0f, mskv = 0.0f;
        if (info) { ind = (float)(info - 1); mskv = 1.0f; }
        out_inds[b * QQ + j] = ind;
        out_mask[b * QQ + j] = mskv;
    }
}

// ---------------------------------------------------------------------------
extern "C" void kernel_launch(void* const* d_in, const int* in_sizes, int n_in,
                              void* d_out, int out_size) {
    const float* sem = (const float*)d_in[0];
    const float* cen = (const float*)d_in[1];
    const float* siz = (const float*)d_in[2];
    const float* gio = (const float*)d_in[3];
    const int*   lab = (const int*)d_in[4];
    const int*   na  = (const int*)d_in[5];

    float* out = (float*)d_out;
    const int NI = BB * QQ;
    const int NC = BB * QQ * GG;

    float* out_inds = out;
    float* out_mask = out + NI;
    float* out_cost = out + 2 * NI;
    bool   do_lsa   = true;
    if (out_size == NC) { out_cost = out; do_lsa = false; }

    cost_kernel<<<BB * 4 * 64, 256>>>(sem, cen, siz, gio, lab, out_cost);
    if (do_lsa) {
        sort_kernel<<<BB * GG, 1024>>>();
        static bool attr_set = false;
        if (!attr_set) {
            cudaFuncSetAttribute(lsa_kernel,
                                 cudaFuncAttributeMaxDynamicSharedMemorySize,
                                 (int)sizeof(SmemLSA));
            attr_set = true;
        }
        lsa_kernel<<<BB, 32, sizeof(SmemLSA)>>>(na, out_cost, out_inds, out_mask);
    }
}

// round 14
// speedup vs baseline: 1.2493x; 1.1099x over previous
#include <cuda_runtime.h>
#include <math.h>

#define BB 8
#define QQ 2048
#define GG 128
#define CC 512
#define TOPK 128     // exactly sufficient: <=127 cols matched at probe time
#define MCW 136      // Mc row stride (floats): 16B-aligned float4, conflict-free
#define M26 0x3FFFFFFull   // low 26 key bits: col(12)|row(7)|slot(7)
#define EPS_AMB 1e-3f      // fp32-selection safety margin (10x worst-case err)

// Transposed cost scratch: [b][g][q], contiguous in q (feeds the sort).
__device__ float g_costT[BB * GG * QQ];
// Per (b,row) sorted smallest-TOPK entries, packed (ord32(val)<<32)|col(1-based).
__device__ unsigned long long g_top[BB * GG * TOPK];

// ---------------------------------------------------------------------------
__device__ __forceinline__ unsigned int ord32(float f) {
    unsigned int u = __float_as_uint(f);
    return (u & 0x80000000u) ? ~u : (u | 0x80000000u);
}
__device__ __forceinline__ float unord32(unsigned int o) {
    unsigned int u = (o & 0x80000000u) ? (o ^ 0x80000000u) : ~o;
    return __uint_as_float(u);
}
__device__ __forceinline__ unsigned long long ord64(double d) {
    unsigned long long u = (unsigned long long)__double_as_longlong(d);
    return (u >> 63) ? ~u : (u | 0x8000000000000000ull);
}

// ---------------------------------------------------------------------------
// Kernel 1: fused focal-class cost + regression costs, tiled transpose.
// ---------------------------------------------------------------------------
__global__ void __launch_bounds__(256)
cost_kernel(const float* __restrict__ sem,
            const float* __restrict__ cen,
            const float* __restrict__ siz,
            const float* __restrict__ gio,
            const int* __restrict__ lab,
            float* __restrict__ out_cost) {
    __shared__ float tile[32][33];
    __shared__ int   lab_s[32];

    int blk = blockIdx.x;                 // (b * 4 + gt) * 64 + qt
    int qt  = blk & 63;
    int gt  = (blk >> 6) & 3;
    int b   = blk >> 8;

    int tx = threadIdx.x & 31;            // g within tile
    int ty = threadIdx.x >> 5;            // q sub-row (0..7)
    int g0 = gt * 32;
    int q0 = qt * 32;

    if (threadIdx.x < 32) lab_s[tx] = lab[b * GG + g0 + tx];
    __syncthreads();

    int l = lab_s[tx];
    #pragma unroll
    for (int s = 0; s < 4; ++s) {
        int ql = ty + 8 * s;
        int q  = q0 + ql;
        long long idx = ((long long)(b * QQ + q)) * GG + g0 + tx;

        float x = sem[((long long)(b * QQ + q)) * CC + l];
        float p   = 1.0f / (1.0f + expf(-x));
        float neg = 0.75f * p * p * (-log1pf(-(p - 1e-8f)));
        float pos = 0.25f * (1.0f - p) * (1.0f - p) * (-logf(p + 1e-8f));
        float cost = 2.0f * (pos - neg) + 5.0f * cen[idx] + siz[idx]
                     - 2.0f * gio[idx];

        out_cost[idx] = cost;
        tile[ql][tx]  = cost;
    }
    __syncthreads();

    #pragma unroll
    for (int s = 0; s < 4; ++s) {
        int gl = ty + 8 * s;
        g_costT[((long long)(b * GG + g0 + gl)) * QQ + q0 + tx] = tile[tx][gl];
    }
}

// ---------------------------------------------------------------------------
// Kernel 2: per (b,row) bitonic sort of 2048 packed keys. Phases jj>=32 in
// shared; phases jj<=16 in registers via shfl (no barriers). Keep TOPK.
// ---------------------------------------------------------------------------
__global__ void __launch_bounds__(1024)
sort_kernel() {
    __shared__ unsigned long long s[QQ];
    const unsigned FULL = 0xffffffffu;
    int tid = threadIdx.x;
    const float* rowp = g_costT + (size_t)blockIdx.x * QQ;

    s[tid] = ((unsigned long long)ord32(rowp[tid]) << 32) |
             (unsigned int)(tid + 1);
    s[tid + 1024] = ((unsigned long long)ord32(rowp[tid + 1024]) << 32) |
                    (unsigned int)(tid + 1024 + 1);
    __syncthreads();

    for (int k = 2; k <= QQ; k <<= 1) {
        for (int jj = k >> 1; jj >= 32; jj >>= 1) {
            int low = tid & (jj - 1);
            int i   = ((tid & ~(jj - 1)) << 1) | low;
            int l   = i | jj;
            unsigned long long a = s[i], c = s[l];
            bool asc = ((i & k) == 0);
            if (asc ? (a > c) : (a < c)) { s[i] = c; s[l] = a; }
            __syncthreads();
        }
        int idx0 = tid, idx1 = tid + 1024;
        unsigned long long e0 = s[idx0], e1 = s[idx1];
        bool asc0 = ((idx0 & k) == 0);
        bool asc1 = ((idx1 & k) == 0);
        int jj0 = (k >> 1 < 32) ? (k >> 1) : 16;
        for (int jj = jj0; jj > 0; jj >>= 1) {
            unsigned long long p0 = __shfl_xor_sync(FULL, e0, jj);
            unsigned long long p1 = __shfl_xor_sync(FULL, e1, jj);
            bool keepmin0 = (((idx0 & jj) == 0) == asc0);
            bool keepmin1 = (((idx1 & jj) == 0) == asc1);
            if (keepmin0 ? (p0 < e0) : (p0 > e0)) e0 = p0;
            if (keepmin1 ? (p1 < e1) : (p1 > e1)) e1 = p1;
        }
        s[idx0] = e0; s[idx1] = e1;
        __syncthreads();
    }
    if (tid < TOPK)
        g_top[(size_t)blockIdx.x * TOPK + tid] = s[tid];
}

// ---------------------------------------------------------------------------
// Kernel 3: one warp per batch; reference's degenerate e-maxx loop.
// v lives in shared (double v_s + float vf_s mirror): deferred v-updates are
// lane-parallel over the chain; selection reads vf via LDS.128 overlapping
// the Mc LDS.128. fp32 selection + exact-fp64 ambiguity fallback; exact fp64
// accounting with warp-uniform winner-key recompute (no shfl).
// ---------------------------------------------------------------------------
struct SmemLSA {
    unsigned long long top_s[GG * TOPK];   // 131072 B (16B-aligned first)
    float  Mc[GG * MCW];                   // row-major [row-1][slot]
    float  vf_s[GG + 4];                   // fp32 mirror of v (16B-aligned)
    double v_s[GG + 2];                    // exact v per slot
    double u_s[GG + 2];
    double Dj[GG + 4];
    int    chain_slot[GG + 4];
    int    chain_row[GG + 4];
    unsigned long long pc[GG + 2];         // raw sorted entry; 0 = invalid
    int    cursor[GG + 2];
    unsigned int colinfo[QQ + 4]; // 0 = unmatched; else row (for ballot/emit)
};

__global__ void __launch_bounds__(32, 1)
lsa_kernel(const int* __restrict__ nactual,
           const float* __restrict__ cost_bqg,
           float* __restrict__ out_inds,
           float* __restrict__ out_mask) {
    extern __shared__ unsigned char smraw[];
    SmemLSA& S = *reinterpret_cast<SmemLSA*>(smraw);

    const unsigned FULL = 0xffffffffu;
    int b    = blockIdx.x;
    int lane = threadIdx.x;
    int n = nactual[b];
    if (n > GG) n = GG;
    if (n < 0) n = 0;

    // preload the full sorted top-list into shared (16B vectorized, coalesced)
    {
        const ulonglong2* src =
            (const ulonglong2*)(g_top + (size_t)b * GG * TOPK);
        ulonglong2* dst = (ulonglong2*)S.top_s;
        #pragma unroll 8
        for (int t = lane; t < GG * TOPK / 2; t += 32)
            dst[t] = __ldg(&src[t]);
    }
    for (int t = lane; t < GG + 2; t += 32) {
        S.u_s[t] = 0.0; S.v_s[t] = 0.0; S.pc[t] = 0ull; S.cursor[t] = 0;
    }
    for (int t = lane; t < GG + 4; t += 32) S.vf_s[t] = 0.0f;
    for (int t = lane; t < QQ + 4; t += 32) S.colinfo[t] = 0u;
    __syncwarp();

    const float* costb = cost_bqg + (size_t)b * QQ * GG;

    // Per-lane: lane owns slots 4*lane..4*lane+3 for um/low_r only.
    unsigned low_r[4];            // col<<14 | (row-1)<<7 | slot
    int mcount = 0;

    for (int i = 1; i <= n; ++i) {
        unsigned um = 0;
        int cl = 1, row = i, j1;
        double D = 0.0;
        if (lane == 0) { S.chain_row[0] = i; S.Dj[0] = 0.0; }
        __syncwarp();

        while (true) {
            // --- probe: cached raw entry; lazy refresh from SMEM top list ---
            unsigned long long pe = S.pc[row];
            unsigned pcc_u, phi;
            if (pe != 0ull) {
                pcc_u = (unsigned)(pe & 0xFFFFFFFFull);
                phi   = (unsigned)(pe >> 32);
            } else {
                const unsigned long long* trow = S.top_s + (row - 1) * TOPK;
                int cur = S.cursor[row];
                unsigned long long ew = 0;
                for (int r = cur >> 5; r < TOPK / 32; ++r) {
                    unsigned long long e = trow[r * 32 + lane];
                    int c = (int)(unsigned int)(e & 0xFFFFFFFFu);
                    unsigned m = __ballot_sync(FULL, S.colinfo[c] == 0u);
                    if (m) {
                        int f = __ffs(m) - 1;
                        ew = __shfl_sync(FULL, e, f);
                        if (lane == 0) { S.cursor[row] = r * 32 + f; S.pc[row] = ew; }
                        break;
                    }
                }
                pcc_u = (unsigned)(ew & 0xFFFFFFFFull);
                phi   = (unsigned)(ew >> 32);
                // no syncwarp needed: all lanes hold ew; later readers of
                // S.pc[row] are past an augmentation __syncwarp.
            }
            float  pval  = unord32(phi);
            double u_row = S.u_s[row];

            // --- fp32 fast keys: Mc LDS.128 + vf LDS.128 (overlapping) ---
            const float4 mc = *(const float4*)&S.Mc[(row - 1) * MCW + 4 * lane];
            const float4 vfq = *(const float4*)&S.vf_s[4 * lane];
            float mcf[4] = {mc.x, mc.y, mc.z, mc.w};
            float vfl[4] = {vfq.x, vfq.y, vfq.z, vfq.w};
            bool  act[4];
            float kf[4];
            unsigned long long kk[4];
            int base = 4 * lane;
            #pragma unroll
            for (int t = 0; t < 4; ++t) {
                act[t] = (base + t < mcount) && !((um >> t) & 1u);
                kf[t]  = act[t] ? (mcf[t] - vfl[t]) : __int_as_float(0x7F800000);
                kk[t]  = ((unsigned long long)ord32(kf[t]) << 32) | low_r[t];
            }
            unsigned long long a0 = (kk[0] < kk[1]) ? kk[0] : kk[1];
            unsigned long long a1 = (kk[2] < kk[3]) ? kk[2] : kk[3];
            unsigned long long bk = (a0 < a1) ? a0 : a1;
            if (lane == 0) {
                unsigned long long kp =
                    ((unsigned long long)phi << 32) | (pcc_u << 14) | 0x7Fu;
                if (kp < bk) bk = kp;
            }

            // --- 2-stage REDUX argmin on fp32 keys ---
            unsigned hi   = (unsigned)(bk >> 32);
            unsigned hmin = __reduce_min_sync(FULL, hi);
            unsigned lo   = (hi == hmin) ? (unsigned)bk : 0xFFFFFFFFu;
            unsigned lmin = __reduce_min_sync(FULL, lo);

            // --- ambiguity check via ballots: >=2 candidates within EPS ---
            float thr = unord32(hmin) + EPS_AMB;
            unsigned cnt = 0;
            #pragma unroll
            for (int t = 0; t < 4; ++t)
                if (act[t] && kf[t] <= thr) ++cnt;
            if (lane == 0 && pval <= thr) ++cnt;
            unsigned m1 = __ballot_sync(FULL, cnt >= 1u);
            unsigned m2 = __ballot_sync(FULL, cnt >= 2u);
            bool ambig = (m2 != 0u) | (__popc(m1) >= 2);

            if (ambig) {
                // --- exact fp64 fallback (v from shared) ---
                unsigned long long k2[4];
                #pragma unroll
                for (int t = 0; t < 4; ++t)
                    k2[t] = act[t]
                        ? ((ord64((double)mcf[t] - S.v_s[base + t]) & ~M26)
                           | low_r[t])
                        : ~0ull;
                unsigned long long c0 = (k2[0] < k2[1]) ? k2[0] : k2[1];
                unsigned long long c1 = (k2[2] < k2[3]) ? k2[2] : k2[3];
                unsigned long long b2 = (c0 < c1) ? c0 : c1;
                if (lane == 0) {
                    unsigned long long kp2 = (ord64((double)pval) & ~M26)
                                             | (pcc_u << 14) | 0x7Fu;
                    if (kp2 < b2) b2 = kp2;
                }
                unsigned h2  = (unsigned)(b2 >> 32);
                unsigned hm2 = __reduce_min_sync(FULL, h2);
                unsigned l2  = (h2 == hm2) ? (unsigned)b2 : 0xFFFFFFFFu;
                lmin = __reduce_min_sync(FULL, l2);
            }

            int slot1 = (int)(lmin & 0x7Fu);
            j1 = (int)((lmin >> 14) & 0xFFFu);

            // --- exact D update, warp-uniform (broadcast LDS, no shfl) ---
            double ek;
            if (slot1 == 0x7F) ek = (double)pval;
            else ek = (double)S.Mc[(row - 1) * MCW + slot1] - S.v_s[slot1];
            D += ek - u_row;

            if (slot1 != 0x7F) {          // chase occupied column
                int nrow = (int)((lmin >> 7) & 0x7Fu) + 1;
                if ((slot1 >> 2) == lane) um |= 1u << (slot1 & 3);
                if (lane == 0) {
                    S.chain_slot[cl] = slot1;
                    S.chain_row[cl]  = nrow;
                    S.Dj[cl]         = D;
                }
                row = nrow;
                ++cl;
            } else break;                 // free column: augment
        }
        __syncwarp();

        // ---- augmentation: issue column LDGs FIRST, bookkeeping in their
        //      shadow, STS last ----
        float mcol[4];
        {
            const float* colp = costb + (size_t)(j1 - 1) * GG;
            #pragma unroll
            for (int m = 0; m < 4; ++m)
                mcol[m] = __ldg(&colp[lane + 32 * m]);
        }
        // deferred u updates (chain rows distinct) — lane-parallel
        for (int t = lane; t < cl; t += 32) {
            S.u_s[S.chain_row[t]] += D - S.Dj[t];
        }
        // deferred v updates (chain slots distinct) — lane-parallel now
        for (int t = 1 + lane; t < cl; t += 32) {
            int s = S.chain_slot[t];
            double nv = S.v_s[s] - (D - S.Dj[t]);
            S.v_s[s]  = nv;
            S.vf_s[s] = (float)nv;
        }
        // invalidate probe caches pointing at the newly matched column
        #pragma unroll
        for (int t = 0; t < 4; ++t) {
            int r = 1 + lane + 32 * t;
            if ((unsigned)(S.pc[r] & 0xFFFFFFFFull) == (unsigned)j1)
                S.pc[r] = 0ull;
        }
        // register the new slot
        if ((mcount >> 2) == lane) {
            unsigned lw = ((unsigned)j1 << 14) | ((unsigned)(i - 1) << 7)
                          | (unsigned)mcount;
            switch (mcount & 3) {
                case 0: low_r[0] = lw; break;
                case 1: low_r[1] = lw; break;
                case 2: low_r[2] = lw; break;
                case 3: low_r[3] = lw; break;
            }
        }
        if (lane == 0) {
            S.v_s[mcount]  = 0.0;         // terminal column: no v update yet
            S.vf_s[mcount] = 0.0f;
            S.colinfo[j1]  = (unsigned)i; // row, for ballot/emit
        }

        // Mc fill last: LDG results have had ~100+ cycles to land
        #pragma unroll
        for (int m = 0; m < 4; ++m)
            S.Mc[(lane + 32 * m) * MCW + mcount] = mcol[m];

        ++mcount;
        __syncwarp();
    }

    // emit per-proposal matches
    for (int j = lane; j < QQ; j += 32) {
        unsigned info = S.colinfo[j + 1];
        float ind = 0.0f, mskv = 0.0f;
        if (info) { ind = (float)(info - 1); mskv = 1.0f; }
        out_inds[b * QQ + j] = ind;
        out_mask[b * QQ + j] = mskv;
    }
}

// ---------------------------------------------------------------------------
extern "C" void kernel_launch(void* const* d_in, const int* in_sizes, int n_in,
                              void* d_out, int out_size) {
    const float* sem = (const float*)d_in[0];
    const float* cen = (const float*)d_in[1];
    const float* siz = (const float*)d_in[2];
    const float* gio = (const float*)d_in[3];
    const int*   lab = (const int*)d_in[4];
    const int*   na  = (const int*)d_in[5];

    float* out = (float*)d_out;
    const int NI = BB * QQ;
    const int NC = BB * QQ * GG;

    float* out_inds = out;
    float* out_mask = out + NI;
    float* out_cost = out + 2 * NI;
    bool   do_lsa   = true;
    if (out_size == NC) { out_cost = out; do_lsa = false; }

    cost_kernel<<<BB * 4 * 64, 256>>>(sem, cen, siz, gio, lab, out_cost);
    if (do_lsa) {
        sort_kernel<<<BB * GG, 1024>>>();
        static bool attr_set = false;
        if (!attr_set) {
            cudaFuncSetAttribute(lsa_kernel,
                                 cudaFuncAttributeMaxDynamicSharedMemorySize,
                                 (int)sizeof(SmemLSA));
            attr_set = true;
        }
        lsa_kernel<<<BB, 32, sizeof(SmemLSA)>>>(na, out_cost, out_inds, out_mask);
    }
}

// round 15
// speedup vs baseline: 1.8827x; 1.5070x over previous
#include <cuda_runtime.h>
#include <math.h>

#define BB 8
#define QQ 2048
#define GG 128
#define CC 512
#define TOPK 128     // exactly sufficient: <=127 cols matched at probe time
#define MCW 136      // Mc row stride (floats): 16B-aligned float4, conflict-free
#define M26 0x3FFFFFFull   // low 26 key bits: col(12)|row(7)|slot(7)
#define EPS_AMB 1e-3f      // fp32-selection safety margin (10x worst-case err)
#define FULLM 0xffffffffu

// Transposed cost scratch: [b][g][q], contiguous in q (feeds the select).
__device__ float g_costT[BB * GG * QQ];
// Per (b,row) sorted smallest-TOPK entries, packed (ord32(val)<<32)|col(1-based).
__device__ unsigned long long g_top[BB * GG * TOPK];

// ---------------------------------------------------------------------------
__device__ __forceinline__ unsigned int ord32(float f) {
    unsigned int u = __float_as_uint(f);
    return (u & 0x80000000u) ? ~u : (u | 0x80000000u);
}
__device__ __forceinline__ float unord32(unsigned int o) {
    unsigned int u = (o & 0x80000000u) ? (o ^ 0x80000000u) : ~o;
    return __uint_as_float(u);
}
__device__ __forceinline__ unsigned long long ord64(double d) {
    unsigned long long u = (unsigned long long)__double_as_longlong(d);
    return (u >> 63) ? ~u : (u | 0x8000000000000000ull);
}

// ---------------------------------------------------------------------------
// Kernel 1: fused focal-class cost + regression costs, tiled transpose.
// ---------------------------------------------------------------------------
__global__ void __launch_bounds__(256)
cost_kernel(const float* __restrict__ sem,
            const float* __restrict__ cen,
            const float* __restrict__ siz,
            const float* __restrict__ gio,
            const int* __restrict__ lab,
            float* __restrict__ out_cost) {
    __shared__ float tile[32][33];
    __shared__ int   lab_s[32];

    int blk = blockIdx.x;                 // (b * 4 + gt) * 64 + qt
    int qt  = blk & 63;
    int gt  = (blk >> 6) & 3;
    int b   = blk >> 8;

    int tx = threadIdx.x & 31;            // g within tile
    int ty = threadIdx.x >> 5;            // q sub-row (0..7)
    int g0 = gt * 32;
    int q0 = qt * 32;

    if (threadIdx.x < 32) lab_s[tx] = lab[b * GG + g0 + tx];
    __syncthreads();

    int l = lab_s[tx];
    #pragma unroll
    for (int s = 0; s < 4; ++s) {
        int ql = ty + 8 * s;
        int q  = q0 + ql;
        long long idx = ((long long)(b * QQ + q)) * GG + g0 + tx;

        float x = sem[((long long)(b * QQ + q)) * CC + l];
        float p   = 1.0f / (1.0f + expf(-x));
        float neg = 0.75f * p * p * (-log1pf(-(p - 1e-8f)));
        float pos = 0.25f * (1.0f - p) * (1.0f - p) * (-logf(p + 1e-8f));
        float cost = 2.0f * (pos - neg) + 5.0f * cen[idx] + siz[idx]
                     - 2.0f * gio[idx];

        out_cost[idx] = cost;
        tile[ql][tx]  = cost;
    }
    __syncthreads();

    #pragma unroll
    for (int s = 0; s < 4; ++s) {
        int gl = ty + 8 * s;
        g_costT[((long long)(b * GG + g0 + gl)) * QQ + q0 + tx] = tile[tx][gl];
    }
}

// ---------------------------------------------------------------------------
// Kernel 2: per (b,row) top-128 select-then-sort.
// 12-bit histogram of ord32 (monotone buckets) -> threshold bucket for the
// 128th element -> compact candidates (cap 2048 = lossless worst case) ->
// small runtime-P bitonic sort -> emit smallest TOPK in (value, col) order.
// ---------------------------------------------------------------------------
__global__ void __launch_bounds__(512)
sort_kernel() {
    __shared__ unsigned int hist[4096];
    __shared__ unsigned long long cand[QQ];
    __shared__ unsigned int warp_sums[16];
    __shared__ int sB, sCnt;

    int tid  = threadIdx.x;
    int lane = tid & 31;
    int warp = tid >> 5;
    const float* rowp = g_costT + (size_t)blockIdx.x * QQ;

    for (int t = tid; t < 4096; t += 512) hist[t] = 0;
    if (tid == 0) sCnt = 0;
    __syncthreads();

    unsigned int o[4];
    #pragma unroll
    for (int t = 0; t < 4; ++t) {
        o[t] = ord32(rowp[tid + 512 * t]);
        atomicAdd(&hist[o[t] >> 20], 1u);
    }
    __syncthreads();

    // block scan over 4096 bins (8 per thread) to locate threshold bucket
    unsigned int binbase = (unsigned)tid * 8u;
    unsigned int bl[8];
    unsigned int p = 0;
    #pragma unroll
    for (int q = 0; q < 8; ++q) { bl[q] = hist[binbase + q]; p += bl[q]; }
    unsigned int inc = p;
    #pragma unroll
    for (int off = 1; off < 32; off <<= 1) {
        unsigned int nb = __shfl_up_sync(FULLM, inc, off);
        if (lane >= off) inc += nb;
    }
    if (lane == 31) warp_sums[warp] = inc;
    __syncthreads();
    if (tid < 16) {
        unsigned int w = warp_sums[tid];
        #pragma unroll
        for (int off = 1; off < 16; off <<= 1) {
            unsigned int nb = __shfl_up_sync(0x0000FFFFu, w, off);
            if (tid >= off) w += nb;
        }
        warp_sums[tid] = w;               // inclusive warp prefix
    }
    __syncthreads();
    unsigned int cstart = inc - p + (warp ? warp_sums[warp - 1] : 0u);
    if (cstart < TOPK && cstart + p >= TOPK) {   // exactly one thread
        unsigned int c = cstart;
        #pragma unroll
        for (int q = 0; q < 8; ++q) {
            c += bl[q];
            if (c >= TOPK) { sB = (int)(binbase + q); break; }
        }
    }
    __syncthreads();
    int B = sB;

    // compact all elements with bucket <= B (superset of the true top-128)
    #pragma unroll
    for (int t = 0; t < 4; ++t) {
        if ((int)(o[t] >> 20) <= B) {
            int idx = atomicAdd(&sCnt, 1);
            cand[idx] = ((unsigned long long)o[t] << 32)
                        | (unsigned)(tid + 512 * t + 1);
        }
    }
    __syncthreads();
    int K = sCnt;                         // >= TOPK by construction
    int P = 256;
    while (P < K) P <<= 1;                // <= 2048 always (cand capacity)
    for (int t = K + tid; t < P; t += 512) cand[t] = ~0ull;
    __syncthreads();

    // bitonic sort P elements (ascending by (value, col))
    for (int k = 2; k <= P; k <<= 1) {
        for (int jj = k >> 1; jj; jj >>= 1) {
            for (int t = tid; t < P / 2; t += 512) {
                int low = t & (jj - 1);
                int i   = ((t & ~(jj - 1)) << 1) | low;
                int l   = i | jj;
                unsigned long long a = cand[i], c = cand[l];
                bool asc = ((i & k) == 0);
                if (asc ? (a > c) : (a < c)) { cand[i] = c; cand[l] = a; }
            }
            __syncthreads();
        }
    }
    if (tid < TOPK)
        g_top[(size_t)blockIdx.x * TOPK + tid] = cand[tid];
}

// ---------------------------------------------------------------------------
// Kernel 3: one warp per batch; reference's degenerate e-maxx loop.
// (unchanged from Round 14 — proven best)
// ---------------------------------------------------------------------------
struct SmemLSA {
    unsigned long long top_s[GG * TOPK];   // 131072 B (16B-aligned first)
    float  Mc[GG * MCW];                   // row-major [row-1][slot]
    float  vf_s[GG + 4];                   // fp32 mirror of v (16B-aligned)
    double v_s[GG + 2];                    // exact v per slot
    double u_s[GG + 2];
    double Dj[GG + 4];
    int    chain_slot[GG + 4];
    int    chain_row[GG + 4];
    unsigned long long pc[GG + 2];         // raw sorted entry; 0 = invalid
    int    cursor[GG + 2];
    unsigned int colinfo[QQ + 4]; // 0 = unmatched; else row (for ballot/emit)
};

__global__ void __launch_bounds__(32, 1)
lsa_kernel(const int* __restrict__ nactual,
           const float* __restrict__ cost_bqg,
           float* __restrict__ out_inds,
           float* __restrict__ out_mask) {
    extern __shared__ unsigned char smraw[];
    SmemLSA& S = *reinterpret_cast<SmemLSA*>(smraw);

    int b    = blockIdx.x;
    int lane = threadIdx.x;
    int n = nactual[b];
    if (n > GG) n = GG;
    if (n < 0) n = 0;

    {
        const ulonglong2* src =
            (const ulonglong2*)(g_top + (size_t)b * GG * TOPK);
        ulonglong2* dst = (ulonglong2*)S.top_s;
        #pragma unroll 8
        for (int t = lane; t < GG * TOPK / 2; t += 32)
            dst[t] = __ldg(&src[t]);
    }
    for (int t = lane; t < GG + 2; t += 32) {
        S.u_s[t] = 0.0; S.v_s[t] = 0.0; S.pc[t] = 0ull; S.cursor[t] = 0;
    }
    for (int t = lane; t < GG + 4; t += 32) S.vf_s[t] = 0.0f;
    for (int t = lane; t < QQ + 4; t += 32) S.colinfo[t] = 0u;
    __syncwarp();

    const float* costb = cost_bqg + (size_t)b * QQ * GG;

    unsigned low_r[4];            // col<<14 | (row-1)<<7 | slot
    int mcount = 0;

    for (int i = 1; i <= n; ++i) {
        unsigned um = 0;
        int cl = 1, row = i, j1;
        double D = 0.0;
        if (lane == 0) { S.chain_row[0] = i; S.Dj[0] = 0.0; }
        __syncwarp();

        while (true) {
            unsigned long long pe = S.pc[row];
            unsigned pcc_u, phi;
            if (pe != 0ull) {
                pcc_u = (unsigned)(pe & 0xFFFFFFFFull);
                phi   = (unsigned)(pe >> 32);
            } else {
                const unsigned long long* trow = S.top_s + (row - 1) * TOPK;
                int cur = S.cursor[row];
                unsigned long long ew = 0;
                for (int r = cur >> 5; r < TOPK / 32; ++r) {
                    unsigned long long e = trow[r * 32 + lane];
                    int c = (int)(unsigned int)(e & 0xFFFFFFFFu);
                    unsigned m = __ballot_sync(FULLM, S.colinfo[c] == 0u);
                    if (m) {
                        int f = __ffs(m) - 1;
                        ew = __shfl_sync(FULLM, e, f);
                        if (lane == 0) { S.cursor[row] = r * 32 + f; S.pc[row] = ew; }
                        break;
                    }
                }
                pcc_u = (unsigned)(ew & 0xFFFFFFFFull);
                phi   = (unsigned)(ew >> 32);
            }
            float  pval  = unord32(phi);
            double u_row = S.u_s[row];

            const float4 mc = *(const float4*)&S.Mc[(row - 1) * MCW + 4 * lane];
            const float4 vfq = *(const float4*)&S.vf_s[4 * lane];
            float mcf[4] = {mc.x, mc.y, mc.z, mc.w};
            float vfl[4] = {vfq.x, vfq.y, vfq.z, vfq.w};
            bool  act[4];
            float kf[4];
            unsigned long long kk[4];
            int base = 4 * lane;
            #pragma unroll
            for (int t = 0; t < 4; ++t) {
                act[t] = (base + t < mcount) && !((um >> t) & 1u);
                kf[t]  = act[t] ? (mcf[t] - vfl[t]) : __int_as_float(0x7F800000);
                kk[t]  = ((unsigned long long)ord32(kf[t]) << 32) | low_r[t];
            }
            unsigned long long a0 = (kk[0] < kk[1]) ? kk[0] : kk[1];
            unsigned long long a1 = (kk[2] < kk[3]) ? kk[2] : kk[3];
            unsigned long long bk = (a0 < a1) ? a0 : a1;
            if (lane == 0) {
                unsigned long long kp =
                    ((unsigned long long)phi << 32) | (pcc_u << 14) | 0x7Fu;
                if (kp < bk) bk = kp;
            }

            unsigned hi   = (unsigned)(bk >> 32);
            unsigned hmin = __reduce_min_sync(FULLM, hi);
            unsigned lo   = (hi == hmin) ? (unsigned)bk : 0xFFFFFFFFu;
            unsigned lmin = __reduce_min_sync(FULLM, lo);

            float thr = unord32(hmin) + EPS_AMB;
            unsigned cnt = 0;
            #pragma unroll
            for (int t = 0; t < 4; ++t)
                if (act[t] && kf[t] <= thr) ++cnt;
            if (lane == 0 && pval <= thr) ++cnt;
            unsigned m1 = __ballot_sync(FULLM, cnt >= 1u);
            unsigned m2 = __ballot_sync(FULLM, cnt >= 2u);
            bool ambig = (m2 != 0u) | (__popc(m1) >= 2);

            if (ambig) {
                unsigned long long k2[4];
                #pragma unroll
                for (int t = 0; t < 4; ++t)
                    k2[t] = act[t]
                        ? ((ord64((double)mcf[t] - S.v_s[base + t]) & ~M26)
                           | low_r[t])
                        : ~0ull;
                unsigned long long c0 = (k2[0] < k2[1]) ? k2[0] : k2[1];
                unsigned long long c1 = (k2[2] < k2[3]) ? k2[2] : k2[3];
                unsigned long long b2 = (c0 < c1) ? c0 : c1;
                if (lane == 0) {
                    unsigned long long kp2 = (ord64((double)pval) & ~M26)
                                             | (pcc_u << 14) | 0x7Fu;
                    if (kp2 < b2) b2 = kp2;
                }
                unsigned h2  = (unsigned)(b2 >> 32);
                unsigned hm2 = __reduce_min_sync(FULLM, h2);
                unsigned l2  = (h2 == hm2) ? (unsigned)b2 : 0xFFFFFFFFu;
                lmin = __reduce_min_sync(FULLM, l2);
            }

            int slot1 = (int)(lmin & 0x7Fu);
            j1 = (int)((lmin >> 14) & 0xFFFu);

            double ek;
            if (slot1 == 0x7F) ek = (double)pval;
            else ek = (double)S.Mc[(row - 1) * MCW + slot1] - S.v_s[slot1];
            D += ek - u_row;

            if (slot1 != 0x7F) {
                int nrow = (int)((lmin >> 7) & 0x7Fu) + 1;
                if ((slot1 >> 2) == lane) um |= 1u << (slot1 & 3);
                if (lane == 0) {
                    S.chain_slot[cl] = slot1;
                    S.chain_row[cl]  = nrow;
                    S.Dj[cl]         = D;
                }
                row = nrow;
                ++cl;
            } else break;
        }
        __syncwarp();

        float mcol[4];
        {
            const float* colp = costb + (size_t)(j1 - 1) * GG;
            #pragma unroll
            for (int m = 0; m < 4; ++m)
                mcol[m] = __ldg(&colp[lane + 32 * m]);
        }
        for (int t = lane; t < cl; t += 32) {
            S.u_s[S.chain_row[t]] += D - S.Dj[t];
        }
        for (int t = 1 + lane; t < cl; t += 32) {
            int s = S.chain_slot[t];
            double nv = S.v_s[s] - (D - S.Dj[t]);
            S.v_s[s]  = nv;
            S.vf_s[s] = (float)nv;
        }
        #pragma unroll
        for (int t = 0; t < 4; ++t) {
            int r = 1 + lane + 32 * t;
            if ((unsigned)(S.pc[r] & 0xFFFFFFFFull) == (unsigned)j1)
                S.pc[r] = 0ull;
        }
        if ((mcount >> 2) == lane) {
            unsigned lw = ((unsigned)j1 << 14) | ((unsigned)(i - 1) << 7)
                          | (unsigned)mcount;
            switch (mcount & 3) {
                case 0: low_r[0] = lw; break;
                case 1: low_r[1] = lw; break;
                case 2: low_r[2] = lw; break;
                case 3: low_r[3] = lw; break;
            }
        }
        if (lane == 0) {
            S.v_s[mcount]  = 0.0;
            S.vf_s[mcount] = 0.0f;
            S.colinfo[j1]  = (unsigned)i;
        }
        #pragma unroll
        for (int m = 0; m < 4; ++m)
            S.Mc[(lane + 32 * m) * MCW + mcount] = mcol[m];

        ++mcount;
        __syncwarp();
    }

    for (int j = lane; j < QQ; j += 32) {
        unsigned info = S.colinfo[j + 1];
        float ind = 0.0f, mskv = 0.0f;
        if (info) { ind = (float)(info - 1); mskv = 1.0f; }
        out_inds[b * QQ + j] = ind;
        out_mask[b * QQ + j] = mskv;
    }
}

// ---------------------------------------------------------------------------
extern "C" void kernel_launch(void* const* d_in, const int* in_sizes, int n_in,
                              void* d_out, int out_size) {
    const float* sem = (const float*)d_in[0];
    const float* cen = (const float*)d_in[1];
    const float* siz = (const float*)d_in[2];
    const float* gio = (const float*)d_in[3];
    const int*   lab = (const int*)d_in[4];
    const int*   na  = (const int*)d_in[5];

    float* out = (float*)d_out;
    const int NI = BB * QQ;
    const int NC = BB * QQ * GG;

    float* out_inds = out;
    float* out_mask = out + NI;
    float* out_cost = out + 2 * NI;
    bool   do_lsa   = true;
    if (out_size == NC) { out_cost = out; do_lsa = false; }

    cost_kernel<<<BB * 4 * 64, 256>>>(sem, cen, siz, gio, lab, out_cost);
    if (do_lsa) {
        sort_kernel<<<BB * GG, 512>>>();
        static bool attr_set = false;
        if (!attr_set) {
            cudaFuncSetAttribute(lsa_kernel,
                                 cudaFuncAttributeMaxDynamicSharedMemorySize,
                                 (int)sizeof(SmemLSA));
            attr_set = true;
        }
        lsa_kernel<<<BB, 32, sizeof(SmemLSA)>>>(na, out_cost, out_inds, out_mask);
    }
}